// round 8
// baseline (speedup 1.0000x reference)
#include <cuda_runtime.h>
#include <math_constants.h>

#define BATCH 16
#define CH    512
#define HGT   128
#define WID   128
#define NS    8

// scratch (no allocs allowed). g_rc is zero-initialized at load; finalize
// re-zeroes it after consuming, so every launch/replay starts from zeros.
__device__ int   g_rc[BATCH * HGT];   // per-(b,h) counts of elements == slice max
__device__ float g_F [BATCH * CH];    // per-(b,c) sum/W

// One block per (b,c) slice of 128x128 floats (64KB).
// 512 threads = 16 warps; warp w handles rows [w*8, w*8+8).
// Phase A: register-resident vector max+sum, single warp reduce, block reduce.
// Phase B: re-scan registers vs vmax; rare atomic per matching element.
__global__ __launch_bounds__(512) void pass1_kernel(const float* __restrict__ x) {
    const int bc   = blockIdx.x;          // 0..B*C-1
    const int b    = bc >> 9;             // / CH
    const int warp = threadIdx.x >> 5;    // 0..15
    const int lane = threadIdx.x & 31;

    const float4* base = reinterpret_cast<const float4*>(x) + (size_t)bc * (HGT * WID / 4);

    // Load 8 float4 (one per row) — independent, front-batched, streaming
    float4 v[8];
    #pragma unroll
    for (int r = 0; r < 8; r++) {
        v[r] = __ldcs(&base[(warp * 8 + r) * 32 + lane]);
    }

    // Vector sum and max trees (FMA pipe only, no shuffles)
    float4 s4 = v[0];
    float4 m4 = v[0];
    #pragma unroll
    for (int r = 1; r < 8; r++) {
        s4.x += v[r].x; s4.y += v[r].y; s4.z += v[r].z; s4.w += v[r].w;
        m4.x = fmaxf(m4.x, v[r].x); m4.y = fmaxf(m4.y, v[r].y);
        m4.z = fmaxf(m4.z, v[r].z); m4.w = fmaxf(m4.w, v[r].w);
    }
    float s = (s4.x + s4.y) + (s4.z + s4.w);
    float m = fmaxf(fmaxf(m4.x, m4.y), fmaxf(m4.z, m4.w));

    // Single warp reduce (10 shuffles total)
    #pragma unroll
    for (int off = 16; off > 0; off >>= 1) {
        s += __shfl_down_sync(0xffffffffu, s, off);
        m  = fmaxf(m, __shfl_down_sync(0xffffffffu, m, off));
    }

    __shared__ float s_wsum[16];
    __shared__ float s_wmax[16];
    __shared__ float s_vmax;
    if (lane == 0) { s_wsum[warp] = s; s_wmax[warp] = m; }
    __syncthreads();

    if (threadIdx.x == 0) {
        float tot = 0.0f, vm = -CUDART_INF_F;
        #pragma unroll
        for (int w = 0; w < 16; w++) { tot += s_wsum[w]; vm = fmaxf(vm, s_wmax[w]); }
        g_F[bc] = tot * (1.0f / (float)WID);
        s_vmax = vm;
    }
    __syncthreads();

    const float vmax = s_vmax;

    // Phase B: count elements equal to the global max, per row.
    // Typically exactly one element in the whole slice matches -> ~1 atomic/block.
    #pragma unroll
    for (int r = 0; r < 8; r++) {
        int c = (v[r].x == vmax) + (v[r].y == vmax) + (v[r].z == vmax) + (v[r].w == vmax);
        if (c) atomicAdd(&g_rc[b * HGT + warp * 8 + r], c);
    }
}

// One block per batch, 512 threads.
// Warp 0: lane-parallel rc load (+reset), 5-step warp-scan exclusive cumsum,
// lane 0 runs the reference-exact sequential threshold scan writing bin edges
// straight into smem (no dynamically-indexed local array). Lanes 0..7 then
// compute exact reciprocals once; the output loop is pure FMUL.
__global__ __launch_bounds__(512) void finalize_kernel(float* __restrict__ out) {
    const int b    = blockIdx.x;
    const int lane = threadIdx.x & 31;

    __shared__ int   s_Hc[HGT];
    __shared__ float s_hks[NS + 1];   // bin edges
    __shared__ float s_hinv[NS];      // 1 / (hks[k+1]-hks[k])

    if (threadIdx.x < 32) {
        // each lane owns rows lane*4 .. lane*4+3
        int rcv[4];
        #pragma unroll
        for (int i = 0; i < 4; i++) {
            const int idx = b * HGT + lane * 4 + i;
            rcv[i] = g_rc[idx];
            g_rc[idx] = 0;                 // reset for next launch/replay
        }
        int l0 = rcv[0];
        int l1 = l0 + rcv[1];
        int l2 = l1 + rcv[2];
        int l3 = l2 + rcv[3];
        // warp exclusive scan of per-lane totals
        int basev = l3;
        #pragma unroll
        for (int off = 1; off < 32; off <<= 1) {
            int t = __shfl_up_sync(0xffffffffu, basev, off);
            if (lane >= off) basev += t;
        }
        basev -= l3;
        s_Hc[lane * 4 + 0] = basev;
        s_Hc[lane * 4 + 1] = basev + l0;
        s_Hc[lane * 4 + 2] = basev + l1;
        s_Hc[lane * 4 + 3] = basev + l2;

        // init bin edges (lanes 0..8)
        if (lane <= NS) s_hks[lane] = (lane == NS) ? (float)HGT : 0.0f;
        __syncwarp();

        if (lane == 0) {
            // reference-exact sequential scan: only one k may fire per j.
            // Edges written straight to smem — no local-memory array.
            int k = 1;
            #pragma unroll
            for (int j = 1; j <= HGT - 2; j++) {
                const int hj  = s_Hc[j];
                const int hj1 = s_Hc[j + 1];
                const int t   = k * (CH / NS);       // k*64
                if (k < NS && hj <= t && hj1 > t) {
                    s_hks[k] = (float)j;
                    k++;
                }
            }
        }
        __syncwarp();

        // exact reciprocal of each bin width, once (8 divides total)
        if (lane < NS) {
            s_hinv[lane] = 1.0f / (s_hks[lane + 1] - s_hks[lane]);
        }
    }
    __syncthreads();

    // 4096 outputs = 1024 float4; 512 threads × 2 float4 each. Pure FMUL.
    const float4* F4 = reinterpret_cast<const float4*>(&g_F[b * CH]);
    float4* ob = reinterpret_cast<float4*>(out + (size_t)b * (NS * CH));
    #pragma unroll
    for (int i = 0; i < 2; i++) {
        const int idx4 = i * 512 + threadIdx.x;      // 0..1023
        const int k    = idx4 >> 7;                  // bin index
        const int c4   = idx4 & 127;                 // float4 index within channels
        const float hi = s_hinv[k];
        float4 f = F4[c4];
        f.x *= hi; f.y *= hi; f.z *= hi; f.w *= hi;
        ob[idx4] = f;
    }
}

extern "C" void kernel_launch(void* const* d_in, const int* in_sizes, int n_in,
                              void* d_out, int out_size) {
    const float* x = (const float*)d_in[0];
    float* out = (float*)d_out;

    pass1_kernel<<<BATCH * CH, 512>>>(x);
    finalize_kernel<<<BATCH, 512>>>(out);
}